// round 16
// baseline (speedup 1.0000x reference)
#include <cuda_runtime.h>
#include <cuda_fp16.h>
#include <math.h>

#define N2    8192
#define BHALF 4096
#define DDIM  128
#define TM    128
#define TN    128
#define NTB   64
#define NT_TRI (NTB * (NTB + 1) / 2)   // 2080 upper-triangle tiles
#define POFF  (BHALF / TM)             // 32
#define APAD  136
#define INV_TEMP 2.0f
#define K2EX  2.885390082f             // 2*log2(e): exp(2x) = 2^(x*K2EX)

__device__ __half g_znh[N2 * DDIM];
__device__ float g_rowsum[N2];
__device__ float g_pos[N2];
__device__ unsigned g_counter;

__device__ __forceinline__ unsigned smem_u32(const void* p) {
    unsigned a;
    asm("{ .reg .u64 t; cvta.to.shared.u64 t, %1; cvt.u32.u64 %0, t; }"
        : "=r"(a) : "l"(p));
    return a;
}
__device__ __forceinline__ float ex2f(float x) {
    float r;
    asm("ex2.approx.f32 %0, %1;" : "=f"(r) : "f"(x));
    return r;
}
__device__ __forceinline__ void ldmatrix_x4(unsigned* r, unsigned addr) {
    asm volatile("ldmatrix.sync.aligned.m8n8.x4.shared.b16 {%0,%1,%2,%3}, [%4];"
                 : "=r"(r[0]), "=r"(r[1]), "=r"(r[2]), "=r"(r[3]) : "r"(addr));
}
__device__ __forceinline__ void ldmatrix_x2(unsigned* r, unsigned addr) {
    asm volatile("ldmatrix.sync.aligned.m8n8.x2.shared.b16 {%0,%1}, [%2];"
                 : "=r"(r[0]), "=r"(r[1]) : "r"(addr));
}
// f16 in, f16 acc: c[0]=(row g, cols q*2,q*2+1), c[1]=(row g+8, same cols)
__device__ __forceinline__ void mma_f16(unsigned* c, const unsigned* a, const unsigned* b) {
    asm volatile(
        "mma.sync.aligned.m16n8k16.row.col.f16.f16.f16.f16 "
        "{%0,%1}, {%2,%3,%4,%5}, {%6,%7}, {%0,%1};"
        : "+r"(c[0]), "+r"(c[1])
        : "r"(a[0]), "r"(a[1]), "r"(a[2]), "r"(a[3]), "r"(b[0]), "r"(b[1]));
}

// ---------------------------------------------------------------------------
// 4 rows per warp, 8 lanes per row, 4 independent float4 loads per thread.
// Zeroes g_rowsum[row]; global thread 0 zeroes the completion counter.
__global__ void __launch_bounds__(256) normalize_kernel(const float* __restrict__ zi,
                                                        const float* __restrict__ zj) {
    const int lane = threadIdx.x & 31;
    const int seg  = lane & 7;                       // lane within row (8)
    const int r    = blockIdx.x * 32 + (threadIdx.x >> 5) * 4 + (lane >> 3);
    const float* src = (r < BHALF) ? (zi + (size_t)r * DDIM)
                                   : (zj + (size_t)(r - BHALF) * DDIM);
    float4 u0 = ((const float4*)src)[seg];
    float4 u1 = ((const float4*)src)[seg + 8];
    float4 u2 = ((const float4*)src)[seg + 16];
    float4 u3 = ((const float4*)src)[seg + 24];
    float ss = u0.x*u0.x + u0.y*u0.y + u0.z*u0.z + u0.w*u0.w
             + u1.x*u1.x + u1.y*u1.y + u1.z*u1.z + u1.w*u1.w
             + u2.x*u2.x + u2.y*u2.y + u2.z*u2.z + u2.w*u2.w
             + u3.x*u3.x + u3.y*u3.y + u3.z*u3.z + u3.w*u3.w;
    #pragma unroll
    for (int o = 1; o <= 4; o <<= 1) ss += __shfl_xor_sync(0xffffffffu, ss, o);
    float inv = rsqrtf(fmaxf(ss, 1e-16f));
    uint2* dst = (uint2*)(g_znh + (size_t)r * DDIM);
    float4 uu[4] = {u0, u1, u2, u3};
    #pragma unroll
    for (int i = 0; i < 4; i++) {
        __half2 pa = __float22half2_rn(make_float2(uu[i].x * inv, uu[i].y * inv));
        __half2 pb = __float22half2_rn(make_float2(uu[i].z * inv, uu[i].w * inv));
        uint2 st;
        st.x = *(unsigned*)&pa;
        st.y = *(unsigned*)&pb;
        dst[seg + 8 * i] = st;
    }
    if (seg == 0) g_rowsum[r] = 0.0f;
    if (blockIdx.x == 0 && threadIdx.x == 0) g_counter = 0u;
}

// ---------------------------------------------------------------------------
// 128x128 tile, 256 threads = 8 warps (4x2), warp tile 32x64, 3 CTAs/SM.
// Upper-triangle grid + one finalizer CTA (blockIdx == NT_TRI) that spin-waits
// on the completion counter and reduces the loss.
__global__ void __launch_bounds__(256, 3) simexp_kernel(float* __restrict__ out) {
    extern __shared__ __half smem[];
    const int tid = threadIdx.x, wid = tid >> 5, lid = tid & 31;

    // ---- finalizer CTA ----
    if (blockIdx.x >= NT_TRI) {
        if (tid == 0) {
            unsigned c;
            do {
                c = *(volatile unsigned*)&g_counter;
                if (c < NT_TRI) __nanosleep(128);
            } while (c < NT_TRI);
        }
        __syncthreads();
        __threadfence();
        float part = 0.0f;
        #pragma unroll 4
        for (int i = tid; i < N2; i += 256)
            part += logf(g_rowsum[i]) - g_pos[i];
        #pragma unroll
        for (int o = 16; o; o >>= 1) part += __shfl_xor_sync(0xffffffffu, part, o);
        float* ws = (float*)smem;
        if (lid == 0) ws[wid] = part;
        __syncthreads();
        if (tid == 0) {
            float t = ws[0] + ws[1] + ws[2] + ws[3] + ws[4] + ws[5] + ws[6] + ws[7];
            out[0] = t * (1.0f / N2);
        }
        return;
    }

    __half* As = smem;                  // [128][APAD]
    __half* Bs = smem + TM * APAD;      // [128][APAD]

    // ---- triangular decode: idx -> (bi, bj), bj >= bi ----
    const int rem = NT_TRI - 1 - (int)blockIdx.x;
    int k = (int)((sqrtf(8.0f * (float)rem + 1.0f) - 1.0f) * 0.5f);
    while ((k + 1) * (k + 2) / 2 <= rem) k++;
    while (k * (k + 1) / 2 > rem) k--;
    const int bi = NTB - 1 - k;
    const int bj = NTB - 1 - (rem - k * (k + 1) / 2);

    const int rowBase = bi * TM;
    const int colBase = bj * TN;
    const int warp_m = (wid & 3) * 32;
    const int warp_n = (wid >> 2) * 64;

    const bool diag = (bi == bj);
    const bool posT = (bj == bi + POFF);

    // ---- load tiles ----
    #pragma unroll
    for (int i = 0; i < 8; i++) {
        int ch = tid + i * 256;
        int r = ch >> 4, c = (ch & 15) * 8;
        *(uint4*)(As + r * APAD + c) =
            *(const uint4*)(g_znh + (size_t)(rowBase + r) * DDIM + c);
        *(uint4*)(Bs + r * APAD + c) =
            *(const uint4*)(g_znh + (size_t)(colBase + r) * DDIM + c);
    }
    __syncthreads();

    const unsigned a_base = smem_u32(As +
        (warp_m + (lid & 15)) * APAD + (lid >> 4) * 8);
    const unsigned b_base = smem_u32(Bs +
        (warp_n + (lid & 7)) * APAD + ((lid >> 3) & 1) * 8);

    unsigned acc[2][8][2] = {};   // f16x2 accumulators

    #pragma unroll
    for (int ks = 0; ks < 8; ks++) {
        const unsigned koff = ks * 32;
        unsigned a0[4], a1[4];
        ldmatrix_x4(a0, a_base + koff);
        ldmatrix_x4(a1, a_base + koff + 16 * APAD * 2);
        #pragma unroll
        for (int nt = 0; nt < 8; nt++) {
            unsigned b[2];
            ldmatrix_x2(b, b_base + koff + nt * 8 * APAD * 2);
            mma_f16(acc[0][nt], a0, b);
            mma_f16(acc[1][nt], a1, b);
        }
    }

    // ---- epilogue ----
    const int g = lid >> 2, q = lid & 3;
    float rsum[2][2] = {};
    float colp[8][2] = {};

    if (diag || posT) {
        // exact scalar f32 path (96 CTAs)
        #pragma unroll
        for (int mt = 0; mt < 2; mt++) {
            const int li0 = warp_m + mt * 16 + g;
            const int li1 = li0 + 8;
            #pragma unroll
            for (int nt = 0; nt < 8; nt++) {
                float2 v0 = __half22float2(*(__half2*)&acc[mt][nt][0]);
                float2 v1 = __half22float2(*(__half2*)&acc[mt][nt][1]);
                const int lj0 = warp_n + nt * 8 + q * 2;
                const int lj1 = lj0 + 1;
                if (diag) {
                    float e0 = ex2f(v0.x * K2EX), e1 = ex2f(v0.y * K2EX);
                    float e2 = ex2f(v1.x * K2EX), e3 = ex2f(v1.y * K2EX);
                    if (lj0 != li0) rsum[mt][0] += e0;
                    if (lj1 != li0) rsum[mt][0] += e1;
                    if (lj0 != li1) rsum[mt][1] += e2;
                    if (lj1 != li1) rsum[mt][1] += e3;
                } else {  // posT: capture positives (sim symmetric), full sums
                    if (lj0 == li0) { float L = v0.x * INV_TEMP;
                        g_pos[rowBase + li0] = L; g_pos[colBase + lj0] = L; }
                    if (lj1 == li0) { float L = v0.y * INV_TEMP;
                        g_pos[rowBase + li0] = L; g_pos[colBase + lj1] = L; }
                    if (lj0 == li1) { float L = v1.x * INV_TEMP;
                        g_pos[rowBase + li1] = L; g_pos[colBase + lj0] = L; }
                    if (lj1 == li1) { float L = v1.y * INV_TEMP;
                        g_pos[rowBase + li1] = L; g_pos[colBase + lj1] = L; }
                    float e0 = ex2f(v0.x * K2EX), e1 = ex2f(v0.y * K2EX);
                    float e2 = ex2f(v1.x * K2EX), e3 = ex2f(v1.y * K2EX);
                    rsum[mt][0] += e0 + e1;
                    rsum[mt][1] += e2 + e3;
                    colp[nt][0] += e0 + e2;
                    colp[nt][1] += e1 + e3;
                }
            }
        }
    } else {
        // packed f16x2 fast path
        const __half2 k2 = __float2half2_rn(K2EX);
        __half2 racc[2][2] = {{__float2half2_rn(0.f), __float2half2_rn(0.f)},
                              {__float2half2_rn(0.f), __float2half2_rn(0.f)}};
        #pragma unroll
        for (int nt = 0; nt < 8; nt++) {
            __half2 cp = __float2half2_rn(0.f);
            #pragma unroll
            for (int mt = 0; mt < 2; mt++) {
                __half2 e0 = h2exp2(__hmul2(*(__half2*)&acc[mt][nt][0], k2));
                __half2 e1 = h2exp2(__hmul2(*(__half2*)&acc[mt][nt][1], k2));
                racc[mt][0] = __hadd2(racc[mt][0], e0);
                racc[mt][1] = __hadd2(racc[mt][1], e1);
                cp = __hadd2(cp, __hadd2(e0, e1));
            }
            float2 cpf = __half22float2(cp);
            colp[nt][0] = cpf.x;
            colp[nt][1] = cpf.y;
        }
        #pragma unroll
        for (int mt = 0; mt < 2; mt++) {
            float2 r0 = __half22float2(racc[mt][0]);
            float2 r1 = __half22float2(racc[mt][1]);
            rsum[mt][0] = r0.x + r0.y;
            rsum[mt][1] = r1.x + r1.y;
        }
    }

    // row sums: reduce over q lanes, one atomic per row fragment
    #pragma unroll
    for (int mt = 0; mt < 2; mt++)
        #pragma unroll
        for (int h = 0; h < 2; h++) {
            float s = rsum[mt][h];
            s += __shfl_xor_sync(0xffffffffu, s, 1);
            s += __shfl_xor_sync(0xffffffffu, s, 2);
            if (q == 0)
                atomicAdd(&g_rowsum[rowBase + warp_m + mt * 16 + h * 8 + g], s);
        }

    // column sums (off-diagonal tiles): reduce over g lanes
    if (!diag) {
        #pragma unroll
        for (int nt = 0; nt < 8; nt++) {
            float s0 = colp[nt][0], s1 = colp[nt][1];
            #pragma unroll
            for (int o = 4; o <= 16; o <<= 1) {
                s0 += __shfl_xor_sync(0xffffffffu, s0, o);
                s1 += __shfl_xor_sync(0xffffffffu, s1, o);
            }
            if (g == 0) {
                const int cj = colBase + warp_n + nt * 8 + q * 2;
                atomicAdd(&g_rowsum[cj],     s0);
                atomicAdd(&g_rowsum[cj + 1], s1);
            }
        }
    }

    // ---- completion signal (threadfence-reduction pattern) ----
    __threadfence();
    __syncthreads();
    if (tid == 0) atomicAdd(&g_counter, 1u);
}

// ---------------------------------------------------------------------------
extern "C" void kernel_launch(void* const* d_in, const int* in_sizes, int n_in,
                              void* d_out, int out_size) {
    const float* zi = (const float*)d_in[0];
    const float* zj = (const float*)d_in[1];
    float* out = (float*)d_out;

    const int smem_bytes = 2 * TM * APAD * (int)sizeof(__half);  // 69632
    cudaFuncSetAttribute(simexp_kernel,
                         cudaFuncAttributeMaxDynamicSharedMemorySize, smem_bytes);

    normalize_kernel<<<N2 / 32, 256>>>(zi, zj);
    simexp_kernel<<<NT_TRI + 1, 256, smem_bytes>>>(out);
}

// round 17
// speedup vs baseline: 1.1382x; 1.1382x over previous
#include <cuda_runtime.h>
#include <cuda_fp16.h>
#include <math.h>

#define N2    8192
#define BHALF 4096
#define DDIM  128
#define TM    128
#define TN    128
#define NTB   64
#define NT_TRI (NTB * (NTB + 1) / 2)   // 2080 upper-triangle tiles
#define POFF  (BHALF / TM)             // 32
#define APAD  136
#define INV_TEMP 2.0f
#define K2EX  2.885390082f             // 2*log2(e): exp(2x) = 2^(x*K2EX)

__device__ __half g_znh[N2 * DDIM];
__device__ float g_rowsum[N2];
__device__ float g_pos[N2];

__device__ __forceinline__ unsigned smem_u32(const void* p) {
    unsigned a;
    asm("{ .reg .u64 t; cvta.to.shared.u64 t, %1; cvt.u32.u64 %0, t; }"
        : "=r"(a) : "l"(p));
    return a;
}
__device__ __forceinline__ float ex2f(float x) {
    float r;
    asm("ex2.approx.f32 %0, %1;" : "=f"(r) : "f"(x));
    return r;
}
__device__ __forceinline__ void ldmatrix_x4(unsigned* r, unsigned addr) {
    asm volatile("ldmatrix.sync.aligned.m8n8.x4.shared.b16 {%0,%1,%2,%3}, [%4];"
                 : "=r"(r[0]), "=r"(r[1]), "=r"(r[2]), "=r"(r[3]) : "r"(addr));
}
__device__ __forceinline__ void ldmatrix_x2(unsigned* r, unsigned addr) {
    asm volatile("ldmatrix.sync.aligned.m8n8.x2.shared.b16 {%0,%1}, [%2];"
                 : "=r"(r[0]), "=r"(r[1]) : "r"(addr));
}
// f16 in, f16 acc: c[0]=(row g, cols q*2,q*2+1), c[1]=(row g+8, same cols)
__device__ __forceinline__ void mma_f16(unsigned* c, const unsigned* a, const unsigned* b) {
    asm volatile(
        "mma.sync.aligned.m16n8k16.row.col.f16.f16.f16.f16 "
        "{%0,%1}, {%2,%3,%4,%5}, {%6,%7}, {%0,%1};"
        : "+r"(c[0]), "+r"(c[1])
        : "r"(a[0]), "r"(a[1]), "r"(a[2]), "r"(a[3]), "r"(b[0]), "r"(b[1]));
}

// ---------------------------------------------------------------------------
// 4 rows per warp, 8 lanes per row, 4 independent float4 loads per thread.
// Zeroes g_rowsum[row]; row-0 lane zeroes out[0] (finalize atomicAdds later).
__global__ void __launch_bounds__(256) normalize_kernel(const float* __restrict__ zi,
                                                        const float* __restrict__ zj,
                                                        float* __restrict__ out) {
    const int lane = threadIdx.x & 31;
    const int seg  = lane & 7;                       // lane within row (8)
    const int r    = blockIdx.x * 32 + (threadIdx.x >> 5) * 4 + (lane >> 3);
    const float* src = (r < BHALF) ? (zi + (size_t)r * DDIM)
                                   : (zj + (size_t)(r - BHALF) * DDIM);
    float4 u0 = ((const float4*)src)[seg];
    float4 u1 = ((const float4*)src)[seg + 8];
    float4 u2 = ((const float4*)src)[seg + 16];
    float4 u3 = ((const float4*)src)[seg + 24];
    float ss = u0.x*u0.x + u0.y*u0.y + u0.z*u0.z + u0.w*u0.w
             + u1.x*u1.x + u1.y*u1.y + u1.z*u1.z + u1.w*u1.w
             + u2.x*u2.x + u2.y*u2.y + u2.z*u2.z + u2.w*u2.w
             + u3.x*u3.x + u3.y*u3.y + u3.z*u3.z + u3.w*u3.w;
    #pragma unroll
    for (int o = 1; o <= 4; o <<= 1) ss += __shfl_xor_sync(0xffffffffu, ss, o);
    float inv = rsqrtf(fmaxf(ss, 1e-16f));
    uint2* dst = (uint2*)(g_znh + (size_t)r * DDIM);
    float4 uu[4] = {u0, u1, u2, u3};
    #pragma unroll
    for (int i = 0; i < 4; i++) {
        __half2 pa = __float22half2_rn(make_float2(uu[i].x * inv, uu[i].y * inv));
        __half2 pb = __float22half2_rn(make_float2(uu[i].z * inv, uu[i].w * inv));
        uint2 st;
        st.x = *(unsigned*)&pa;
        st.y = *(unsigned*)&pb;
        dst[seg + 8 * i] = st;
    }
    if (seg == 0) {
        g_rowsum[r] = 0.0f;
        if (r == 0) out[0] = 0.0f;
    }
}

// ---------------------------------------------------------------------------
// 128x128 tile, 128 threads = 4 warps (2x2), warp tile 64x64, 3 CTAs/SM.
// Upper-triangle grid; off-diag tiles feed row AND column sums (symmetry).
__global__ void __launch_bounds__(128, 3) simexp_kernel() {
    extern __shared__ __half smem[];
    __half* As = smem;                  // [128][APAD]
    __half* Bs = smem + TM * APAD;      // [128][APAD]

    // ---- triangular decode: idx -> (bi, bj), bj >= bi ----
    const int rem = NT_TRI - 1 - (int)blockIdx.x;
    int k = (int)((sqrtf(8.0f * (float)rem + 1.0f) - 1.0f) * 0.5f);
    while ((k + 1) * (k + 2) / 2 <= rem) k++;
    while (k * (k + 1) / 2 > rem) k--;
    const int bi = NTB - 1 - k;
    const int bj = NTB - 1 - (rem - k * (k + 1) / 2);

    const int tid = threadIdx.x, wid = tid >> 5, lid = tid & 31;
    const int rowBase = bi * TM;
    const int colBase = bj * TN;
    const int warp_m = (wid & 1) * 64;
    const int warp_n = (wid >> 1) * 64;

    const bool diag = (bi == bj);
    const bool posT = (bj == bi + POFF);

    // ---- load tiles: 2048 16B-chunks per panel, 16 per thread ----
    #pragma unroll
    for (int i = 0; i < 16; i++) {
        int ch = tid + i * 128;
        int r = ch >> 4, c = (ch & 15) * 8;
        *(uint4*)(As + r * APAD + c) =
            *(const uint4*)(g_znh + (size_t)(rowBase + r) * DDIM + c);
        *(uint4*)(Bs + r * APAD + c) =
            *(const uint4*)(g_znh + (size_t)(colBase + r) * DDIM + c);
    }
    __syncthreads();

    const unsigned a_base = smem_u32(As +
        (warp_m + (lid & 15)) * APAD + (lid >> 4) * 8);
    const unsigned b_base = smem_u32(Bs +
        (warp_n + (lid & 7)) * APAD + ((lid >> 3) & 1) * 8);

    unsigned acc[4][8][2] = {};   // f16x2 accumulators (64 regs)

    #pragma unroll
    for (int ks = 0; ks < 8; ks++) {
        const unsigned koff = ks * 32;
        unsigned a[4][4];
        #pragma unroll
        for (int mt = 0; mt < 4; mt++)
            ldmatrix_x4(a[mt], a_base + koff + mt * 16 * APAD * 2);
        #pragma unroll
        for (int nt = 0; nt < 8; nt++) {
            unsigned b[2];
            ldmatrix_x2(b, b_base + koff + nt * 8 * APAD * 2);
            #pragma unroll
            for (int mt = 0; mt < 4; mt++)
                mma_f16(acc[mt][nt], a[mt], b);
        }
    }

    // ---- epilogue ----
    const int g = lid >> 2, q = lid & 3;
    float rsum[4][2] = {};
    float colp[8][2] = {};

    if (diag || posT) {
        // exact scalar f32 path (96 CTAs)
        #pragma unroll
        for (int mt = 0; mt < 4; mt++) {
            const int li0 = warp_m + mt * 16 + g;
            const int li1 = li0 + 8;
            #pragma unroll
            for (int nt = 0; nt < 8; nt++) {
                float2 v0 = __half22float2(*(__half2*)&acc[mt][nt][0]);
                float2 v1 = __half22float2(*(__half2*)&acc[mt][nt][1]);
                const int lj0 = warp_n + nt * 8 + q * 2;
                const int lj1 = lj0 + 1;
                if (diag) {
                    float e0 = ex2f(v0.x * K2EX), e1 = ex2f(v0.y * K2EX);
                    float e2 = ex2f(v1.x * K2EX), e3 = ex2f(v1.y * K2EX);
                    if (lj0 != li0) rsum[mt][0] += e0;
                    if (lj1 != li0) rsum[mt][0] += e1;
                    if (lj0 != li1) rsum[mt][1] += e2;
                    if (lj1 != li1) rsum[mt][1] += e3;
                } else {  // posT: capture positives (sim symmetric), full sums
                    if (lj0 == li0) { float L = v0.x * INV_TEMP;
                        g_pos[rowBase + li0] = L; g_pos[colBase + lj0] = L; }
                    if (lj1 == li0) { float L = v0.y * INV_TEMP;
                        g_pos[rowBase + li0] = L; g_pos[colBase + lj1] = L; }
                    if (lj0 == li1) { float L = v1.x * INV_TEMP;
                        g_pos[rowBase + li1] = L; g_pos[colBase + lj0] = L; }
                    if (lj1 == li1) { float L = v1.y * INV_TEMP;
                        g_pos[rowBase + li1] = L; g_pos[colBase + lj1] = L; }
                    float e0 = ex2f(v0.x * K2EX), e1 = ex2f(v0.y * K2EX);
                    float e2 = ex2f(v1.x * K2EX), e3 = ex2f(v1.y * K2EX);
                    rsum[mt][0] += e0 + e1;
                    rsum[mt][1] += e2 + e3;
                    colp[nt][0] += e0 + e2;
                    colp[nt][1] += e1 + e3;
                }
            }
        }
    } else {
        // packed f16x2 fast path
        const __half2 k2 = __float2half2_rn(K2EX);
        __half2 racc[4][2];
        #pragma unroll
        for (int mt = 0; mt < 4; mt++)
            racc[mt][0] = racc[mt][1] = __float2half2_rn(0.f);
        #pragma unroll
        for (int nt = 0; nt < 8; nt++) {
            __half2 cp = __float2half2_rn(0.f);
            #pragma unroll
            for (int mt = 0; mt < 4; mt++) {
                __half2 e0 = h2exp2(__hmul2(*(__half2*)&acc[mt][nt][0], k2));
                __half2 e1 = h2exp2(__hmul2(*(__half2*)&acc[mt][nt][1], k2));
                racc[mt][0] = __hadd2(racc[mt][0], e0);
                racc[mt][1] = __hadd2(racc[mt][1], e1);
                cp = __hadd2(cp, __hadd2(e0, e1));
            }
            float2 cpf = __half22float2(cp);
            colp[nt][0] = cpf.x;
            colp[nt][1] = cpf.y;
        }
        #pragma unroll
        for (int mt = 0; mt < 4; mt++) {
            float2 r0 = __half22float2(racc[mt][0]);
            float2 r1 = __half22float2(racc[mt][1]);
            rsum[mt][0] = r0.x + r0.y;
            rsum[mt][1] = r1.x + r1.y;
        }
    }

    // row sums: reduce over q lanes, one atomic per row fragment
    #pragma unroll
    for (int mt = 0; mt < 4; mt++)
        #pragma unroll
        for (int h = 0; h < 2; h++) {
            float s = rsum[mt][h];
            s += __shfl_xor_sync(0xffffffffu, s, 1);
            s += __shfl_xor_sync(0xffffffffu, s, 2);
            if (q == 0)
                atomicAdd(&g_rowsum[rowBase + warp_m + mt * 16 + h * 8 + g], s);
        }

    // column sums (off-diagonal tiles): reduce over g lanes
    if (!diag) {
        #pragma unroll
        for (int nt = 0; nt < 8; nt++) {
            float s0 = colp[nt][0], s1 = colp[nt][1];
            #pragma unroll
            for (int o = 4; o <= 16; o <<= 1) {
                s0 += __shfl_xor_sync(0xffffffffu, s0, o);
                s1 += __shfl_xor_sync(0xffffffffu, s1, o);
            }
            if (g == 0) {
                const int cj = colBase + warp_n + nt * 8 + q * 2;
                atomicAdd(&g_rowsum[cj],     s0);
                atomicAdd(&g_rowsum[cj + 1], s1);
            }
        }
    }
}

// ---------------------------------------------------------------------------
__global__ void finalize_kernel(float* out) {
    int i = blockIdx.x * blockDim.x + threadIdx.x;
    float val = logf(g_rowsum[i]) - g_pos[i];
    #pragma unroll
    for (int o = 16; o; o >>= 1) val += __shfl_xor_sync(0xffffffffu, val, o);
    __shared__ float ws[8];
    int lane = threadIdx.x & 31, w = threadIdx.x >> 5;
    if (lane == 0) ws[w] = val;
    __syncthreads();
    if (w == 0) {
        float v = (lane < 8) ? ws[lane] : 0.0f;
        #pragma unroll
        for (int o = 4; o; o >>= 1) v += __shfl_xor_sync(0xffffffffu, v, o);
        if (lane == 0) atomicAdd(out, v * (1.0f / N2));
    }
}

// ---------------------------------------------------------------------------
extern "C" void kernel_launch(void* const* d_in, const int* in_sizes, int n_in,
                              void* d_out, int out_size) {
    const float* zi = (const float*)d_in[0];
    const float* zj = (const float*)d_in[1];
    float* out = (float*)d_out;

    const int smem_bytes = 2 * TM * APAD * (int)sizeof(__half);  // 69632
    cudaFuncSetAttribute(simexp_kernel,
                         cudaFuncAttributeMaxDynamicSharedMemorySize, smem_bytes);

    normalize_kernel<<<N2 / 32, 256>>>(zi, zj, out);
    simexp_kernel<<<NT_TRI, 128, smem_bytes>>>();
    finalize_kernel<<<N2 / 256, 256>>>(out);
}